// round 3
// baseline (speedup 1.0000x reference)
#include <cuda_runtime.h>
#include <math.h>

#define NANCH     331776      // 192*192*9
#define NGT       64
#define MAXACC    300
#define NMS_THR   0.7f
#define BG_THR    0.5f
#define NUM_CLS   20.0f

#define BINS        512
#define BSHIFT      14
#define POOL_TARGET 7424
#define POOL_CAP    8192
#define SORTN       8192
#define CHUNK       1024
#define NWORDS      (CHUNK/64)   // 16

typedef unsigned long long u64;
typedef unsigned int u32;

// ---------------- static device scratch ----------------
// [0..BINS) histogram, [BINS] poolCount, [BINS+1] cutoffKey
__device__ u32 g_scratch[BINS + 8];
__device__ u64 g_pool[POOL_CAP];

// ---------------- kernel 1: 512-bin histogram of score keys ----------------
__global__ void hist_kernel(const float* __restrict__ confs) {
    __shared__ u32 sh[BINS];
    for (int b = threadIdx.x; b < BINS; b += blockDim.x) sh[b] = 0;
    __syncthreads();
    const float4* c4 = (const float4*)confs;
    const int n4 = NANCH / 4;
    for (int i = blockIdx.x * blockDim.x + threadIdx.x; i < n4; i += gridDim.x * blockDim.x) {
        float4 v = c4[i];
        float cc[4] = {v.x, v.y, v.z, v.w};
        #pragma unroll
        for (int k = 0; k < 4; ++k) {
            float c = cc[k];
            if (c > 0.5f) {
                u32 key = __float_as_uint(c) - 0x3F000000u;
                u32 b = key >> BSHIFT; if (b > BINS - 1) b = BINS - 1;
                atomicAdd(&sh[b], 1u);
            }
        }
    }
    __syncthreads();
    for (int b = threadIdx.x; b < BINS; b += blockDim.x)
        if (sh[b]) atomicAdd(&g_scratch[b], sh[b]);
}

// ---------------- kernel 2: find cutoff bucket (1 block, BINS threads) ----------------
__global__ void cutoff_kernel() {
    __shared__ u32 A[BINS], B[BINS];
    int t = threadIdx.x;
    A[t] = g_scratch[BINS - 1 - t];          // reversed so prefix-scan = suffix-sum
    __syncthreads();
    u32 *src = A, *dst = B;
    for (int off = 1; off < BINS; off <<= 1) {
        u32 v = src[t];
        if (t >= off) v += src[t - off];
        dst[t] = v;
        __syncthreads();
        u32* tmp = src; src = dst; dst = tmp;
    }
    u32 total = src[BINS - 1];
    u32 T = total < POOL_TARGET ? total : POOL_TARGET;
    if (T > 0) {
        int b = t;
        u32 suf = src[BINS - 1 - b];
        u32 sufNext = (b == BINS - 1) ? 0u : src[BINS - 1 - (b + 1)];
        if (suf >= T && sufNext < T)
            g_scratch[BINS + 1] = ((u32)b) << BSHIFT;   // cutoff key
    }
    // T==0: cutoffKey stays 0 from memset; pool will be empty anyway
}

// ---------------- kernel 3: compact top candidates into pool ----------------
__global__ void compact_kernel(const float* __restrict__ confs) {
    int i4 = blockIdx.x * blockDim.x + threadIdx.x;
    if (i4 >= NANCH / 4) return;
    float4 v = ((const float4*)confs)[i4];
    u32 cutoff = g_scratch[BINS + 1];
    float cc[4] = {v.x, v.y, v.z, v.w};
    #pragma unroll
    for (int k = 0; k < 4; ++k) {
        float c = cc[k];
        if (c > 0.5f) {
            u32 key = __float_as_uint(c) - 0x3F000000u;   // >= 1
            if (key >= cutoff) {
                u32 pos = atomicAdd(&g_scratch[BINS], 1u);
                if (pos < POOL_CAP) {
                    u32 idx = (u32)(i4 * 4 + k);
                    g_pool[pos] = ((u64)key << 19) | (u64)(0x7FFFFu - idx);
                }
            }
        }
    }
}

// ---------------- division-free IoU>thr test ----------------
__device__ __forceinline__ bool iou_gt(const float4& a, float aArea, const float4& b) {
    float tlx = fmaxf(a.x, b.x), tly = fmaxf(a.y, b.y);
    float brx = fminf(a.z, b.z), bry = fminf(a.w, b.w);
    float w = fmaxf(brx - tlx, 0.0f), h = fmaxf(bry - tly, 0.0f);
    float inter = w * h;
    float uni = aArea + (b.z - b.x) * (b.w - b.y) - inter + 1e-9f;
    return inter > NMS_THR * uni;
}

// ---------------- smem layout for sort+NMS kernel ----------------
#define OFF_KEY   0
#define OFF_MASK  (OFF_KEY + SORTN * 8)              // 65536
#define OFF_BOX   (OFF_MASK + CHUNK * NWORDS * 8)    // 196608
#define OFF_ACC   (OFF_BOX + CHUNK * 16)             // 212992
#define OFF_SEL   (OFF_ACC + 304 * 16)               // 217856
#define OFF_GT    (OFF_SEL + 304 * 8)                // 220288
#define OFF_GTC   (OFF_GT + NGT * 16)                // 221312
#define OFF_BAL   (OFF_GTC + 256)                    // 221568
#define OFF_MISC  (OFF_BAL + 128)                    // 221696
#define SMEM_TOTAL (OFF_MISC + 64)                   // 221760

// ---------------- kernel 4: sort pool + greedy NMS + outputs ----------------
__global__ __launch_bounds__(1024, 1)
void sortnms_kernel(const float* __restrict__ deltas,
                    const float* __restrict__ anchors,
                    const float* __restrict__ gts,
                    const float* __restrict__ gtc,
                    float* __restrict__ out) {
    extern __shared__ unsigned char smem[];
    u64*    sKey   = (u64*)(smem + OFF_KEY);
    u64*    sMask  = (u64*)(smem + OFF_MASK);
    float4* sBox   = (float4*)(smem + OFF_BOX);
    float4* sAcc   = (float4*)(smem + OFF_ACC);
    u64*    sSel   = (u64*)(smem + OFF_SEL);
    float4* sGt    = (float4*)(smem + OFF_GT);
    float*  sGtCls = (float*)(smem + OFF_GTC);
    u32*    sBal   = (u32*)(smem + OFF_BAL);
    int*    sMisc  = (int*)(smem + OFF_MISC);

    const int tid = threadIdx.x;
    u32 P = g_scratch[BINS]; if (P > POOL_CAP) P = POOL_CAP;

    // load pool, pad with 0
    for (int i = tid; i < SORTN; i += 1024)
        sKey[i] = (i < (int)P) ? g_pool[i] : 0ull;
    if (tid < NGT) {
        float4 g = ((const float4*)gts)[tid];
        sGt[tid] = make_float4(g.x - 0.5f * g.z, g.y - 0.5f * g.w,
                               g.x + 0.5f * g.z, g.y + 0.5f * g.w);
        sGtCls[tid] = gtc[tid];
    }
    if (tid == 0) sMisc[0] = 0;
    __syncthreads();

    // bitonic sort descending (padding zeros sink to the end)
    for (int k = 2; k <= SORTN; k <<= 1) {
        for (int j = k >> 1; j > 0; j >>= 1) {
            for (int i = tid; i < SORTN; i += 1024) {
                int ixj = i ^ j;
                if (ixj > i) {
                    u64 a = sKey[i], b = sKey[ixj];
                    if (((i & k) == 0) ? (a < b) : (a > b)) { sKey[i] = b; sKey[ixj] = a; }
                }
            }
            __syncthreads();
        }
    }

    // greedy NMS over sorted chunks
    for (int base = 0; base < SORTN; base += CHUNK) {
        int nAcc = sMisc[0];
        if (nAcc >= MAXACC) break;
        if (sKey[base] == 0ull) break;       // chunk head invalid -> rest invalid (uniform)

        u64 comp = sKey[base + tid];
        bool cand = (comp >> 19) != 0ull;
        float4 box = make_float4(0.f, 0.f, 0.f, 0.f);
        float myArea = 0.f;
        if (cand) {
            u32 a = 0x7FFFFu - (u32)(comp & 0x7FFFFu);
            float4 d  = ((const float4*)deltas)[a];
            float4 an = ((const float4*)anchors)[a];
            float cx = d.x * an.z + an.x;
            float cy = d.y * an.w + an.y;
            float hw = 0.5f * expf(d.z) * an.z;
            float hh = 0.5f * expf(d.w) * an.w;
            box = make_float4(cx - hw, cy - hh, cx + hw, cy + hh);
            myArea = (box.z - box.x) * (box.w - box.y);
        }
        sBox[tid] = box;

        // pre-filter against accepted boxes from earlier chunks
        bool alive = cand;
        for (int q = 0; q < nAcc && alive; ++q)
            if (iou_gt(box, myArea, sAcc[q])) alive = false;

        u32 bal = __ballot_sync(0xffffffffu, alive);
        if ((tid & 31) == 0) sBal[tid >> 5] = bal;
        __syncthreads();

        // transposed mask: column j holds bits i (>j) that j suppresses
        {
            const int j = tid;
            #pragma unroll
            for (int w = 0; w < NWORDS; ++w) {
                u64 m = 0ull;
                if (alive) {
                    int start = j + 1 > (w << 6) ? j + 1 : (w << 6);
                    int end = (w << 6) + 64;
                    for (int i = start; i < end; ++i) {
                        // validity of i not needed: dead bits are masked out of aliveW
                        if (iou_gt(box, myArea, sBox[i])) m |= (1ull << (i & 63));
                    }
                }
                sMask[j * NWORDS + w] = m;
            }
        }
        __syncthreads();

        // warp-0 serial acceptance: work only per acceptance
        if (tid < 32) {
            const int lane = tid;
            u64 aliveW = 0ull;
            if (lane < NWORDS) {
                u32 lo = sBal[lane * 2], hi = sBal[lane * 2 + 1];
                aliveW = ((u64)hi << 32) | (u64)lo;
            }
            int cnt = nAcc;
            while (cnt < MAXACC) {
                int bit = aliveW ? (__ffsll((long long)aliveW) - 1) : 64;
                u32 jl = (lane < NWORDS && bit < 64) ? (u32)((lane << 6) + bit) : 0xffffffffu;
                u32 j = __reduce_min_sync(0xffffffffu, jl);
                if (j == 0xffffffffu) break;
                if (lane == 0) {
                    sAcc[cnt] = sBox[j];
                    sSel[cnt] = sKey[base + j];
                }
                if (lane == (int)(j >> 6)) aliveW &= ~(1ull << (j & 63));
                if (lane < NWORDS) aliveW &= ~sMask[j * NWORDS + lane];
                ++cnt;
            }
            if (lane == 0) sMisc[0] = cnt;
        }
        __syncthreads();
    }

    __syncthreads();
    const int nAcc = sMisc[0];

    // outputs: confs[300] | yxminmax[300,4] | cls[300]
    for (int k = tid; k < MAXACC; k += 1024) {
        if (k < nAcc) {
            u64 comp = sSel[k];
            out[k] = __uint_as_float((u32)(comp >> 19) + 0x3F000000u);
            float4 b = sAcc[k];
            out[MAXACC + 4 * k + 0] = b.y;   // ymin
            out[MAXACC + 4 * k + 1] = b.x;   // xmin
            out[MAXACC + 4 * k + 2] = b.w;   // ymax
            out[MAXACC + 4 * k + 3] = b.z;   // xmax
            float bArea = (b.z - b.x) * (b.w - b.y);
            float best = -1.0f; int bi = 0;
            for (int g = 0; g < NGT; ++g) {
                float4 gb = sGt[g];
                float tlx = fmaxf(b.x, gb.x), tly = fmaxf(b.y, gb.y);
                float brx = fminf(b.z, gb.z), bry = fminf(b.w, gb.w);
                float w = fmaxf(brx - tlx, 0.0f), h = fmaxf(bry - tly, 0.0f);
                float inter = w * h;
                float v = inter / (bArea + (gb.z - gb.x) * (gb.w - gb.y) - inter + 1e-9f);
                if (v > best) { best = v; bi = g; }
            }
            out[MAXACC * 5 + k] = (best < BG_THR) ? NUM_CLS : sGtCls[bi];
        } else {
            out[k] = 0.0f;
            out[MAXACC + 4 * k + 0] = 0.0f;
            out[MAXACC + 4 * k + 1] = 0.0f;
            out[MAXACC + 4 * k + 2] = 0.0f;
            out[MAXACC + 4 * k + 3] = 0.0f;
            out[MAXACC * 5 + k] = NUM_CLS;
        }
    }
}

// ---------------- host launcher ----------------
extern "C" void kernel_launch(void* const* d_in, const int* in_sizes, int n_in,
                              void* d_out, int out_size) {
    const float* confs   = (const float*)d_in[0];
    const float* deltas  = (const float*)d_in[1];
    const float* anchors = (const float*)d_in[2];
    const float* gts     = (const float*)d_in[3];
    const float* gtc     = (const float*)d_in[4];
    float* out = (float*)d_out;

    void* scratch;
    cudaGetSymbolAddress(&scratch, g_scratch);

    static int smem_set = 0;
    if (!smem_set) {
        cudaFuncSetAttribute(sortnms_kernel,
                             cudaFuncAttributeMaxDynamicSharedMemorySize, SMEM_TOTAL);
        smem_set = 1;
    }

    cudaMemsetAsync(scratch, 0, (BINS + 8) * sizeof(u32));
    hist_kernel<<<64, 256>>>(confs);
    cutoff_kernel<<<1, BINS>>>();
    compact_kernel<<<(NANCH / 4 + 255) / 256, 256>>>(confs);
    sortnms_kernel<<<1, 1024, SMEM_TOTAL>>>(deltas, anchors, gts, gtc, out);
}

// round 4
// speedup vs baseline: 1.0648x; 1.0648x over previous
#include <cuda_runtime.h>
#include <math.h>

typedef unsigned long long u64;
typedef unsigned int u32;

#define NANCH   331776      // 192*192*9
#define NGT     64
#define MAXACC  300
#define NMS_THR 0.7f
#define BG_THR  0.5f
#define NUM_CLS 20.0f

#define BINS        512
#define BSHIFT      15          // key in [1, 0x800000] -> bucket in [0, 256]
#define POOL_TARGET 7424
#define POOL_CAP    8192
#define NW          (POOL_CAP/64)   // 128 words per mask row

// ---------------- static device scratch ----------------
__device__ u32 g_hist[BINS];
__device__ u32 g_off[BINS];         // bucket start offsets; reused as cursors by compact
__device__ u32 g_meta[8];           // [0]=P [1]=cutKey [2]=cutBucket [3]=junk
__device__ u64 g_pool[POOL_CAP];
__device__ float4 g_boxes[POOL_CAP];
__device__ float  g_area[POOL_CAP];
__device__ u64 g_mask[(size_t)POOL_CAP * NW];   // 8 MB suppression matrix

// ---------------- kernel 1: histogram of 24-bit score keys ----------------
__global__ void hist_kernel(const float* __restrict__ confs) {
    __shared__ u32 sh[BINS];
    for (int b = threadIdx.x; b < BINS; b += blockDim.x) sh[b] = 0;
    __syncthreads();
    const float4* c4 = (const float4*)confs;
    const int n4 = NANCH / 4;
    for (int i = blockIdx.x * blockDim.x + threadIdx.x; i < n4; i += gridDim.x * blockDim.x) {
        float4 v = c4[i];
        float cc[4] = {v.x, v.y, v.z, v.w};
        #pragma unroll
        for (int k = 0; k < 4; ++k) {
            float c = cc[k];
            if (c > 0.5f) {
                u32 key = __float_as_uint(c) - 0x3F000000u;
                u32 b = key >> BSHIFT; if (b > BINS - 1) b = BINS - 1;
                atomicAdd(&sh[b], 1u);
            }
        }
    }
    __syncthreads();
    for (int b = threadIdx.x; b < BINS; b += blockDim.x)
        if (sh[b]) atomicAdd(&g_hist[b], sh[b]);
}

// ---------------- kernel 2: cutoff bucket + per-bucket offsets ----------------
__global__ void cutoff_kernel() {
    __shared__ u32 A[BINS], B[BINS];
    int t = threadIdx.x;
    A[t] = g_hist[BINS - 1 - t];            // reversed -> prefix scan = suffix sum
    __syncthreads();
    u32 *src = A, *dst = B;
    for (int off = 1; off < BINS; off <<= 1) {
        u32 v = src[t];
        if (t >= off) v += src[t - off];
        dst[t] = v;
        __syncthreads();
        u32* tmp = src; src = dst; dst = tmp;
    }
    int b = t;
    u32 isuf = src[BINS - 1 - b];           // sum of buckets >= b
    u32 cnt  = g_hist[b];
    u32 off  = isuf - cnt;                  // sum of buckets > b = start offset
    g_off[b] = off;
    u32 total = src[BINS - 1];
    u32 T = total < POOL_TARGET ? total : POOL_TARGET;
    if (T > 0 && off < T && isuf >= T) {
        u32 P = isuf; if (P > POOL_CAP) P = POOL_CAP;
        g_meta[0] = P;
        g_meta[1] = ((u32)b) << BSHIFT;
        g_meta[2] = (u32)b;
    }
}

// ---------------- kernel 3: compact into per-bucket segments ----------------
__global__ void compact_kernel(const float* __restrict__ confs) {
    int i4 = blockIdx.x * blockDim.x + threadIdx.x;
    if (i4 >= NANCH / 4) return;
    float4 v = ((const float4*)confs)[i4];
    u32 cutoff = g_meta[1];
    float cc[4] = {v.x, v.y, v.z, v.w};
    #pragma unroll
    for (int k = 0; k < 4; ++k) {
        float c = cc[k];
        if (c > 0.5f) {
            u32 key = __float_as_uint(c) - 0x3F000000u;   // >= 1
            if (key >= cutoff && cutoff > 0) {
                u32 b = key >> BSHIFT; if (b > BINS - 1) b = BINS - 1;
                u32 pos = atomicAdd(&g_off[b], 1u);
                if (pos < POOL_CAP) {
                    u32 idx = (u32)(i4 * 4 + k);
                    g_pool[pos] = ((u64)key << 19) | (u64)(0x7FFFFu - idx);
                }
            }
        }
    }
}

// ---------------- kernel 4: per-bucket bitonic sort + box decode ----------------
__global__ __launch_bounds__(256)
void sortdecode_kernel(const float* __restrict__ deltas,
                       const float* __restrict__ anchors) {
    const int b = blockIdx.x;
    const u32 P = g_meta[0];
    if (P == 0) return;
    u32 cb = g_meta[2];
    u32 cnt = g_hist[b];
    if ((u32)b < cb || cnt == 0) return;
    u32 off = g_off[b] - g_hist[b];   // cursor advanced by exactly hist[b]
    if (off >= POOL_CAP) return;
    if (cnt > 1024) cnt = 1024;
    if (off + cnt > POOL_CAP) cnt = POOL_CAP - off;

    __shared__ u64 s[1024];
    const int t = threadIdx.x;
    for (int i = t; i < 1024; i += 256)
        s[i] = (i < (int)cnt) ? g_pool[off + i] : 0ull;
    __syncthreads();
    for (int k = 2; k <= 1024; k <<= 1) {
        for (int j = k >> 1; j > 0; j >>= 1) {
            for (int i = t; i < 1024; i += 256) {
                int ixj = i ^ j;
                if (ixj > i) {
                    u64 a = s[i], bb = s[ixj];
                    if (((i & k) == 0) ? (a < bb) : (a > bb)) { s[i] = bb; s[ixj] = a; }
                }
            }
            __syncthreads();
        }
    }
    // write back sorted segment + decode boxes
    for (int i = t; i < (int)cnt; i += 256) {
        u64 comp = s[i];
        g_pool[off + i] = comp;
        u32 idx = 0x7FFFFu - (u32)(comp & 0x7FFFFu);
        float4 d  = ((const float4*)deltas)[idx];
        float4 an = ((const float4*)anchors)[idx];
        float cx = d.x * an.z + an.x;
        float cy = d.y * an.w + an.y;
        float hw = 0.5f * expf(d.z) * an.z;
        float hh = 0.5f * expf(d.w) * an.w;
        float4 box = make_float4(cx - hw, cy - hh, cx + hw, cy + hh);
        g_boxes[off + i] = box;
        g_area[off + i] = (box.z - box.x) * (box.w - box.y);
    }
}

// ---------------- kernel 5: suppression bit-matrix (upper triangle) ----------------
__device__ __forceinline__ bool iou_gt(const float4& a, float aArea,
                                       const float4& b, float bArea) {
    float tlx = fmaxf(a.x, b.x), tly = fmaxf(a.y, b.y);
    float brx = fminf(a.z, b.z), bry = fminf(a.w, b.w);
    float w = fmaxf(brx - tlx, 0.0f), h = fmaxf(bry - tly, 0.0f);
    float inter = w * h;
    float uni = aArea + bArea - inter + 1e-9f;
    return inter > NMS_THR * uni;
}

__global__ __launch_bounds__(64)
void matrix_kernel() {
    const int bx = blockIdx.x;   // col tile / word index
    const int by = blockIdx.y;   // row tile
    if (bx < by) return;
    const u32 P = g_meta[0];
    __shared__ float4 cB[64];
    __shared__ float  cA[64];
    const int t = threadIdx.x;
    int j = (bx << 6) + t;
    bool jv = (u32)j < P;
    cB[t] = jv ? g_boxes[j] : make_float4(0.f, 0.f, 0.f, 0.f);
    cA[t] = jv ? g_area[j] : 0.f;
    __syncthreads();
    int i = (by << 6) + t;
    if ((u32)i >= P) return;
    float4 bb = g_boxes[i];
    float  ba = g_area[i];
    u64 m = 0ull;
    #pragma unroll 8
    for (int b = 0; b < 64; ++b) {
        int j2 = (bx << 6) + b;
        if (j2 > i && iou_gt(bb, ba, cB[b], cA[b]))
            m |= (1ull << b);
    }
    g_mask[(size_t)i * NW + bx] = m;
}

// ---------------- kernel 6: serial resolution (bit-ops only) + outputs ----------------
__global__ __launch_bounds__(128, 1)
void resolve_kernel(const float* __restrict__ gts,
                    const float* __restrict__ gtc,
                    const float* __restrict__ confsUnused,
                    float* __restrict__ out) {
    __shared__ u64 remv[NW];
    __shared__ int sAcc[MAXACC];
    __shared__ float4 sGt[NGT];
    __shared__ float  sGtc[NGT];
    __shared__ int sN;

    const int t = threadIdx.x;
    const u32 P = g_meta[0];
    if (t < NW) {
        u32 base = (u32)t * 64u;
        u64 v;
        if (base >= P) v = ~0ull;
        else { u32 r = P - base; v = (r >= 64) ? 0ull : ~((1ull << r) - 1ull); }
        remv[t] = v;
    }
    if (t < NGT) {
        float4 g = ((const float4*)gts)[t];
        sGt[t] = make_float4(g.x - 0.5f * g.z, g.y - 0.5f * g.w,
                             g.x + 0.5f * g.z, g.y + 0.5f * g.w);
        sGtc[t] = gtc[t];
    }
    if (t == 0) sN = 0;
    __syncthreads();

    if (t < 32) {
        const int lane = t;
        int cnt = 0;
        u64 junk = 0ull;
        for (int w = 0; w < NW && cnt < MAXACC; ++w) {
            u64 cand = ~remv[w];
            while (cand && cnt < MAXACC) {
                int b = __ffsll((long long)cand) - 1;
                int c = (w << 6) + b;
                if (lane == 0) sAcc[cnt] = c;
                ++cnt;
                u64 hmask = (b == 63) ? 0ull : ~((2ull << b) - 1ull);
                u64 rest = cand & hmask;
                // speculative prefetch of likely-next row (hides L2 latency)
                if (rest) {
                    int b2 = __ffsll((long long)rest) - 1;
                    int c2 = (w << 6) + b2;
                    const ulonglong2* pr =
                        (const ulonglong2*)&g_mask[(size_t)c2 * NW + (lane << 2)];
                    ulonglong2 s0 = __ldg(pr);
                    ulonglong2 s1 = __ldg(pr + 1);
                    junk ^= s0.x ^ s1.y;
                }
                const ulonglong2* p =
                    (const ulonglong2*)&g_mask[(size_t)c * NW + (lane << 2)];
                ulonglong2 r0 = __ldg(p);
                ulonglong2 r1 = __ldg(p + 1);
                remv[(lane << 2) + 0] |= r0.x;
                remv[(lane << 2) + 1] |= r0.y;
                remv[(lane << 2) + 2] |= r1.x;
                remv[(lane << 2) + 3] |= r1.y;
                __syncwarp();
                cand = (~remv[w]) & hmask;
            }
        }
        if (lane == 0) { sN = cnt; g_meta[3] = (u32)junk; }
    }
    __syncthreads();
    const int nAcc = sN;

    // outputs: confs[300] | yxminmax[300,4] | cls[300]
    for (int k = t; k < MAXACC; k += 128) {
        if (k < nAcc) {
            int c = sAcc[k];
            u64 comp = g_pool[c];
            out[k] = __uint_as_float((u32)(comp >> 19) + 0x3F000000u);
            float4 bb = g_boxes[c];
            out[MAXACC + 4 * k + 0] = bb.y;   // ymin
            out[MAXACC + 4 * k + 1] = bb.x;   // xmin
            out[MAXACC + 4 * k + 2] = bb.w;   // ymax
            out[MAXACC + 4 * k + 3] = bb.z;   // xmax
            float bArea = (bb.z - bb.x) * (bb.w - bb.y);
            float best = -1.0f; int bi = 0;
            for (int g = 0; g < NGT; ++g) {
                float4 gb = sGt[g];
                float tlx = fmaxf(bb.x, gb.x), tly = fmaxf(bb.y, gb.y);
                float brx = fminf(bb.z, gb.z), bry = fminf(bb.w, gb.w);
                float w = fmaxf(brx - tlx, 0.0f), h = fmaxf(bry - tly, 0.0f);
                float inter = w * h;
                float v = inter / (bArea + (gb.z - gb.x) * (gb.w - gb.y) - inter + 1e-9f);
                if (v > best) { best = v; bi = g; }
            }
            out[MAXACC * 5 + k] = (best < BG_THR) ? NUM_CLS : sGtc[bi];
        } else {
            out[k] = 0.0f;
            out[MAXACC + 4 * k + 0] = 0.0f;
            out[MAXACC + 4 * k + 1] = 0.0f;
            out[MAXACC + 4 * k + 2] = 0.0f;
            out[MAXACC + 4 * k + 3] = 0.0f;
            out[MAXACC * 5 + k] = NUM_CLS;
        }
    }
}

// ---------------- host launcher ----------------
extern "C" void kernel_launch(void* const* d_in, const int* in_sizes, int n_in,
                              void* d_out, int out_size) {
    const float* confs   = (const float*)d_in[0];
    const float* deltas  = (const float*)d_in[1];
    const float* anchors = (const float*)d_in[2];
    const float* gts     = (const float*)d_in[3];
    const float* gtc     = (const float*)d_in[4];
    float* out = (float*)d_out;

    void *histA, *metaA;
    cudaGetSymbolAddress(&histA, g_hist);
    cudaGetSymbolAddress(&metaA, g_meta);

    cudaMemsetAsync(histA, 0, BINS * sizeof(u32));
    cudaMemsetAsync(metaA, 0, 8 * sizeof(u32));
    hist_kernel<<<64, 256>>>(confs);
    cutoff_kernel<<<1, BINS>>>();
    compact_kernel<<<(NANCH / 4 + 255) / 256, 256>>>(confs);
    sortdecode_kernel<<<BINS, 256>>>(deltas, anchors);
    matrix_kernel<<<dim3(NW, NW), 64>>>();
    resolve_kernel<<<1, 128>>>(gts, gtc, confs, out);
}

// round 5
// speedup vs baseline: 2.5143x; 2.3613x over previous
#include <cuda_runtime.h>
#include <math.h>

typedef unsigned long long u64;
typedef unsigned int u32;

#define NANCH   331776      // 192*192*9
#define NGT     64
#define MAXACC  300
#define NMS_THR 0.7f
#define BG_THR  0.5f
#define NUM_CLS 20.0f

#define BINS        4096
#define BSHIFT      11          // key in [1, 0x800000) -> bin [0, 4095]
#define POOL_TARGET 1100
#define POOL_CAP    1216
#define MASKW       19          // 1216/64
#define SORTN       2048
#define HIST_BLOCKS 64

// meta slots appended after histogram (single memset covers all)
#define M_P      (BINS+0)
#define M_CUT    (BINS+1)
#define M_VALID  (BINS+2)
#define M_CURSOR (BINS+3)
#define M_DONE   (BINS+4)

__device__ u32 g_hist[BINS + 8];
__device__ u64 g_pool[POOL_CAP];
__device__ float4 g_boxes[POOL_CAP];
__device__ float  g_area[POOL_CAP];
__device__ __align__(16) u64 g_mask[POOL_CAP * MASKW];

// ---------------- kernel 1: histogram + (last block) cutoff selection ----------------
__global__ __launch_bounds__(256)
void histcut_kernel(const float* __restrict__ confs) {
    __shared__ u32 sh[BINS];
    const int t = threadIdx.x;
    for (int b = t; b < BINS; b += 256) sh[b] = 0;
    __syncthreads();
    const float4* c4 = (const float4*)confs;
    const int n4 = NANCH / 4;
    for (int i = blockIdx.x * 256 + t; i < n4; i += HIST_BLOCKS * 256) {
        float4 v = c4[i];
        float cc[4] = {v.x, v.y, v.z, v.w};
        #pragma unroll
        for (int k = 0; k < 4; ++k) {
            float c = cc[k];
            if (c > 0.5f) {
                u32 key = __float_as_uint(c) - 0x3F000000u;
                u32 b = key >> BSHIFT; if (b > BINS - 1) b = BINS - 1;
                atomicAdd(&sh[b], 1u);
            }
        }
    }
    __syncthreads();
    for (int b = t; b < BINS; b += 256)
        if (sh[b]) atomicAdd(&g_hist[b], sh[b]);
    __threadfence();
    __syncthreads();
    __shared__ u32 sLast;
    if (t == 0) sLast = atomicAdd(&g_hist[M_DONE], 1u);
    __syncthreads();
    if (sLast != HIST_BLOCKS - 1) return;

    // ---- last block: suffix-sum scan over reversed bins, find cutoff ----
    u32 v[16], incl[16];
    u32 tsum = 0;
    #pragma unroll
    for (int k = 0; k < 16; ++k) {
        int ridx = t * 16 + k;               // reversed position
        v[k] = __ldcg(&g_hist[BINS - 1 - ridx]);
        tsum += v[k];
        incl[k] = tsum;
    }
    __syncthreads();                          // done with sh as histogram
    sh[t] = tsum;
    __syncthreads();
    for (int off = 1; off < 256; off <<= 1) {
        u32 x = sh[t];
        u32 y = (t >= off) ? sh[t - off] : 0u;
        __syncthreads();
        sh[t] = x + y;
        __syncthreads();
    }
    u32 total = sh[255];
    u32 excl = sh[t] - tsum;
    u32 T = total < POOL_TARGET ? total : POOL_TARGET;
    if (T > 0) {
        #pragma unroll
        for (int k = 0; k < 16; ++k) {
            u32 inc = excl + incl[k];
            if (inc >= T && inc - v[k] < T) {     // unique crossing (v[k] > 0)
                u32 b = (u32)(BINS - 1 - (t * 16 + k));
                if (inc <= POOL_CAP) {
                    g_hist[M_P]   = inc;
                    g_hist[M_CUT] = b << BSHIFT;
                } else {                           // crossing bin too fat: drop it
                    g_hist[M_P]   = inc - v[k];
                    g_hist[M_CUT] = (b + 1) << BSHIFT;
                }
                g_hist[M_VALID] = 1u;
            }
        }
    }
}

// ---------------- kernel 2: compact candidates >= cutoff ----------------
__global__ __launch_bounds__(256)
void compact_kernel(const float* __restrict__ confs) {
    int i4 = blockIdx.x * 256 + threadIdx.x;
    if (i4 >= NANCH / 4) return;
    float4 v = ((const float4*)confs)[i4];
    u32 valid = g_hist[M_VALID];
    u32 cutoff = g_hist[M_CUT];
    float cc[4] = {v.x, v.y, v.z, v.w};
    #pragma unroll
    for (int k = 0; k < 4; ++k) {
        float c = cc[k];
        if (c > 0.5f) {
            u32 key = __float_as_uint(c) - 0x3F000000u;   // >= 1
            if (valid && key >= cutoff) {
                u32 pos = atomicAdd(&g_hist[M_CURSOR], 1u);
                if (pos < POOL_CAP) {
                    u32 idx = (u32)(i4 * 4 + k);
                    g_pool[pos] = ((u64)key << 19) | (u64)(0x7FFFFu - idx);
                }
            }
        }
    }
}

// ---------------- kernel 3: single-block bitonic sort + box decode ----------------
__global__ __launch_bounds__(1024, 1)
void sortdecode_kernel(const float* __restrict__ deltas,
                       const float* __restrict__ anchors) {
    __shared__ u64 s[SORTN];
    const int t = threadIdx.x;
    u32 P = g_hist[M_P]; if (P > POOL_CAP) P = POOL_CAP;
    for (int i = t; i < SORTN; i += 1024)
        s[i] = (i < (int)P) ? g_pool[i] : 0ull;
    __syncthreads();
    for (int k = 2; k <= SORTN; k <<= 1) {
        for (int j = k >> 1; j > 0; j >>= 1) {
            #pragma unroll
            for (int r = 0; r < SORTN / 1024; ++r) {
                int i = t + r * 1024;
                int ixj = i ^ j;
                if (ixj > i) {
                    u64 a = s[i], b = s[ixj];
                    if (((i & k) == 0) ? (a < b) : (a > b)) { s[i] = b; s[ixj] = a; }
                }
            }
            __syncthreads();
        }
    }
    for (int i = t; i < (int)P; i += 1024) {
        u64 comp = s[i];
        g_pool[i] = comp;
        u32 idx = 0x7FFFFu - (u32)(comp & 0x7FFFFu);
        float4 d  = ((const float4*)deltas)[idx];
        float4 an = ((const float4*)anchors)[idx];
        float cx = d.x * an.z + an.x;
        float cy = d.y * an.w + an.y;
        float hw = 0.5f * expf(d.z) * an.z;
        float hh = 0.5f * expf(d.w) * an.w;
        float4 box = make_float4(cx - hw, cy - hh, cx + hw, cy + hh);
        g_boxes[i] = box;
        g_area[i] = (box.z - box.x) * (box.w - box.y);
    }
}

// ---------------- kernel 4: suppression bit-matrix ----------------
__device__ __forceinline__ bool iou_gt(const float4& a, float aArea,
                                       const float4& b, float bArea) {
    float tlx = fmaxf(a.x, b.x), tly = fmaxf(a.y, b.y);
    float brx = fminf(a.z, b.z), bry = fminf(a.w, b.w);
    float w = fmaxf(brx - tlx, 0.0f), h = fmaxf(bry - tly, 0.0f);
    float inter = w * h;
    float uni = aArea + bArea - inter + 1e-9f;
    return inter > NMS_THR * uni;
}

__global__ __launch_bounds__(64)
void matrix_kernel() {
    const int bx = blockIdx.x;   // word (column tile)
    const int by = blockIdx.y;   // row tile
    const u32 P = g_hist[M_P] > POOL_CAP ? POOL_CAP : g_hist[M_P];
    __shared__ float4 cB[64];
    __shared__ float  cA[64];
    const int t = threadIdx.x;
    int j = (bx << 6) + t;
    bool jv = (u32)j < P;
    cB[t] = jv ? g_boxes[j] : make_float4(0.f, 0.f, 0.f, 0.f);
    cA[t] = jv ? g_area[j] : 0.f;
    __syncthreads();
    int i = (by << 6) + t;
    if ((u32)i >= P) return;
    float4 bb = g_boxes[i];
    float  ba = g_area[i];
    u64 m = 0ull;
    #pragma unroll 8
    for (int b = 0; b < 64; ++b) {
        int j2 = (bx << 6) + b;
        if (j2 > i && iou_gt(bb, ba, cB[b], cA[b]))
            m |= (1ull << b);
    }
    g_mask[i * MASKW + bx] = m;
}

// ---------------- kernel 5: in-smem bitmask resolve + outputs ----------------
#define OFF_M    0
#define OFF_GT   (POOL_CAP * MASKW * 8)          // 184832
#define OFF_GTC  (OFF_GT + NGT * 16)             // 185856
#define OFF_ACC  (OFF_GTC + 256)                 // 186112
#define OFF_N    (OFF_ACC + MAXACC * 4)          // 187312
#define RSMEM    (OFF_N + 16)                    // 187328

__global__ __launch_bounds__(1024, 1)
void resolve_kernel(const float* __restrict__ gts,
                    const float* __restrict__ gtc,
                    float* __restrict__ out) {
    extern __shared__ unsigned char smem[];
    u64*    sM    = (u64*)(smem + OFF_M);
    float4* sGt   = (float4*)(smem + OFF_GT);
    float*  sGtc  = (float*)(smem + OFF_GTC);
    u32*    sAcc  = (u32*)(smem + OFF_ACC);
    int*    sN    = (int*)(smem + OFF_N);

    const int t = threadIdx.x;
    u32 P = g_hist[M_P]; if (P > POOL_CAP) P = POOL_CAP;

    // preload mask rows [0, P) into shared (linear, row-major)
    const int W = (int)P * MASKW;
    for (int w = t; w < W; w += 1024) sM[w] = g_mask[w];
    if (t < NGT) {
        float4 g = ((const float4*)gts)[t];
        sGt[t] = make_float4(g.x - 0.5f * g.z, g.y - 0.5f * g.w,
                             g.x + 0.5f * g.z, g.y + 0.5f * g.w);
        sGtc[t] = gtc[t];
    }
    if (t == 0) *sN = 0;
    __syncthreads();

    if (t < 32) {
        const int lane = t;
        u64 avail = 0ull;
        if (lane < MASKW) {
            int base = lane << 6;
            int rem = (int)P - base;
            avail = (rem >= 64) ? ~0ull : (rem <= 0 ? 0ull : ((1ull << rem) - 1ull));
        }
        int cnt = 0;
        while (cnt < MAXACC) {
            int local = avail ? (__ffsll((long long)avail) - 1) : 64;
            u32 cj = (local < 64) ? (u32)((lane << 6) + local) : 0xFFFFFFFFu;
            u32 j = __reduce_min_sync(0xffffffffu, cj);
            if (j == 0xFFFFFFFFu) break;
            if (lane == 0) sAcc[cnt] = j;
            ++cnt;
            if (lane < MASKW) avail &= ~sM[j * MASKW + lane];
            if (lane == (int)(j >> 6)) avail &= ~(1ull << (j & 63));
        }
        if (lane == 0) *sN = cnt;
    }
    __syncthreads();
    const int nAcc = *sN;

    // outputs: confs[300] | yxminmax[300,4] | cls[300]
    for (int k = t; k < MAXACC; k += 1024) {
        if (k < nAcc) {
            u32 c = sAcc[k];
            u64 comp = g_pool[c];
            out[k] = __uint_as_float((u32)(comp >> 19) + 0x3F000000u);
            float4 bb = g_boxes[c];
            out[MAXACC + 4 * k + 0] = bb.y;   // ymin
            out[MAXACC + 4 * k + 1] = bb.x;   // xmin
            out[MAXACC + 4 * k + 2] = bb.w;   // ymax
            out[MAXACC + 4 * k + 3] = bb.z;   // xmax
            float bArea = (bb.z - bb.x) * (bb.w - bb.y);
            float best = -1.0f; int bi = 0;
            for (int g = 0; g < NGT; ++g) {
                float4 gb = sGt[g];
                float tlx = fmaxf(bb.x, gb.x), tly = fmaxf(bb.y, gb.y);
                float brx = fminf(bb.z, gb.z), bry = fminf(bb.w, gb.w);
                float w = fmaxf(brx - tlx, 0.0f), h = fmaxf(bry - tly, 0.0f);
                float inter = w * h;
                float v = inter / (bArea + (gb.z - gb.x) * (gb.w - gb.y) - inter + 1e-9f);
                if (v > best) { best = v; bi = g; }
            }
            out[MAXACC * 5 + k] = (best < BG_THR) ? NUM_CLS : sGtc[bi];
        } else {
            out[k] = 0.0f;
            out[MAXACC + 4 * k + 0] = 0.0f;
            out[MAXACC + 4 * k + 1] = 0.0f;
            out[MAXACC + 4 * k + 2] = 0.0f;
            out[MAXACC + 4 * k + 3] = 0.0f;
            out[MAXACC * 5 + k] = NUM_CLS;
        }
    }
}

// ---------------- host launcher ----------------
extern "C" void kernel_launch(void* const* d_in, const int* in_sizes, int n_in,
                              void* d_out, int out_size) {
    const float* confs   = (const float*)d_in[0];
    const float* deltas  = (const float*)d_in[1];
    const float* anchors = (const float*)d_in[2];
    const float* gts     = (const float*)d_in[3];
    const float* gtc     = (const float*)d_in[4];
    float* out = (float*)d_out;

    void* histA;
    cudaGetSymbolAddress(&histA, g_hist);

    static int inited = 0;
    if (!inited) {
        cudaFuncSetAttribute(resolve_kernel,
                             cudaFuncAttributeMaxDynamicSharedMemorySize, RSMEM);
        inited = 1;
    }

    cudaMemsetAsync(histA, 0, (BINS + 8) * sizeof(u32));
    histcut_kernel<<<HIST_BLOCKS, 256>>>(confs);
    compact_kernel<<<(NANCH / 4 + 255) / 256, 256>>>(confs);
    sortdecode_kernel<<<1, 1024>>>(deltas, anchors);
    matrix_kernel<<<dim3(MASKW, MASKW), 64>>>();
    resolve_kernel<<<1, 1024, RSMEM>>>(gts, gtc, out);
}